// round 7
// baseline (speedup 1.0000x reference)
#include <cuda_runtime.h>
#include <cstdint>

typedef unsigned long long u64;

// ---------- packed f32x2 helpers ----------
__device__ __forceinline__ u64 pk2(float lo, float hi) {
    u64 r;
    asm("mov.b64 %0, {%1, %2};" : "=l"(r)
        : "r"(__float_as_uint(lo)), "r"(__float_as_uint(hi)));
    return r;
}
__device__ __forceinline__ void upk(u64 a, float& lo, float& hi) {
    unsigned int l_, h_;
    asm("mov.b64 {%0, %1}, %2;" : "=r"(l_), "=r"(h_) : "l"(a));
    lo = __uint_as_float(l_);
    hi = __uint_as_float(h_);
}
__device__ __forceinline__ u64 dfma(u64 a, u64 b, u64 c) {
    u64 d;
    asm("fma.rn.f32x2 %0, %1, %2, %3;" : "=l"(d) : "l"(a), "l"(b), "l"(c));
    return d;
}
__device__ __forceinline__ u64 dmul(u64 a, u64 b) {
    u64 d;
    asm("mul.rn.f32x2 %0, %1, %2;" : "=l"(d) : "l"(a), "l"(b));
    return d;
}
__device__ __forceinline__ u64 dadd(u64 a, u64 b) {
    u64 d;
    asm("add.rn.f32x2 %0, %1, %2;" : "=l"(d) : "l"(a), "l"(b));
    return d;
}
// 2*relu(x) per half, exact: x + |x| (2x folded into pre-halved W2/W3)
__device__ __forceinline__ u64 drelu2(u64 a) {
    return dadd(a, a & 0x7FFFFFFF7FFFFFFFULL);
}
__device__ __forceinline__ uint32_t smem_u32(const void* p) {
    uint32_t a;
    asm("{ .reg .u64 t; cvta.to.shared.u64 t, %1; cvt.u32.u64 %0, t; }"
        : "=r"(a) : "l"(p));
    return a;
}
__device__ __forceinline__ void ldsw2(uint32_t addr, u64& a, u64& b) {
    asm("ld.shared.v2.u64 {%0, %1}, [%2];" : "=l"(a), "=l"(b) : "r"(addr));
}
__device__ __forceinline__ void lds_f2(uint32_t addr, float& a, float& b) {
    asm("ld.shared.v2.f32 {%0, %1}, [%2];" : "=f"(a), "=f"(b) : "r"(addr));
}
__device__ __forceinline__ void cp16(uint32_t dst, const char* src, bool pred) {
    if (pred)
        asm volatile("cp.async.cg.shared.global [%0], [%1], 16;"
                     :: "r"(dst), "l"(src) : "memory");
}
__device__ __forceinline__ void cp_commit() {
    asm volatile("cp.async.commit_group;" ::: "memory");
}
__device__ __forceinline__ void cp_wait2() {
    asm volatile("cp.async.wait_group 2;" ::: "memory");
}

// Weight smem layout (u64 packed (v,v)), ordered for paired loads:
//  [4j..4j+3] = W1[j,0..2], b1[j]   [20+6j..] = .5*W2[j,0..4], b2[j]
//  [50..55]   = .5*W3[0..4], b3
__device__ __forceinline__ void pair_step(
    u64 ax, u64 ay, u64 az,
    u64 npx, u64 npy, u64 npz,
    uint32_t swb,
    u64& vx, u64& vy, u64& vz)
{
    u64 dx = dadd(ax, npx);
    u64 dy = dadd(ay, npy);
    u64 dz = dadd(az, npz);
    u64 d2 = dfma(dx, dx, dfma(dy, dy, dmul(dz, dz)));
    float a, b;
    upk(d2, a, b);
    float ia = rsqrtf(fmaxf(a, 1e-24f));   // matches v/max(||v||,1e-12)
    float ib = rsqrtf(fmaxf(b, 1e-24f));

    // Layer 1 on the UNNORMALIZED diff (overlaps the MUFU rsqrt)
    u64 wa, wb, wc, B0, B1, B2, B3, B4;
    u64 u0, u1, u2, u3, u4;
    ldsw2(swb + 0 * 8, wa, wb); ldsw2(swb + 2 * 8, wc, B0);
    u0 = dfma(dz, wc, dfma(dy, wb, dmul(dx, wa)));
    ldsw2(swb + 4 * 8, wa, wb); ldsw2(swb + 6 * 8, wc, B1);
    u1 = dfma(dz, wc, dfma(dy, wb, dmul(dx, wa)));
    ldsw2(swb + 8 * 8, wa, wb); ldsw2(swb + 10 * 8, wc, B2);
    u2 = dfma(dz, wc, dfma(dy, wb, dmul(dx, wa)));
    ldsw2(swb + 12 * 8, wa, wb); ldsw2(swb + 14 * 8, wc, B3);
    u3 = dfma(dz, wc, dfma(dy, wb, dmul(dx, wa)));
    ldsw2(swb + 16 * 8, wa, wb); ldsw2(swb + 18 * 8, wc, B4);
    u4 = dfma(dz, wc, dfma(dy, wb, dmul(dx, wa)));

    u64 inv = pk2(ia, ib);
    u64 h0 = drelu2(dfma(u0, inv, B0));
    u64 h1 = drelu2(dfma(u1, inv, B1));
    u64 h2 = drelu2(dfma(u2, inv, B2));
    u64 h3 = drelu2(dfma(u3, inv, B3));
    u64 h4 = drelu2(dfma(u4, inv, B4));

    u64 wd, we, bj;
    u64 g0, g1, g2, g3, g4;
#define L2ROW(G, OFF)                                                       \
    ldsw2(swb + (OFF) * 8, wa, wb); ldsw2(swb + ((OFF) + 2) * 8, wc, wd);   \
    ldsw2(swb + ((OFF) + 4) * 8, we, bj);                                   \
    G = dfma(h0, wa, bj); G = dfma(h1, wb, G); G = dfma(h2, wc, G);         \
    G = dfma(h3, wd, G);  G = dfma(h4, we, G); G = drelu2(G);
    L2ROW(g0, 20) L2ROW(g1, 26) L2ROW(g2, 32) L2ROW(g3, 38) L2ROW(g4, 44)
#undef L2ROW

    ldsw2(swb + 50 * 8, wa, wb);
    ldsw2(swb + 52 * 8, wc, wd);
    ldsw2(swb + 54 * 8, we, bj);
    u64 wgt = dfma(g0, wa, bj);
    wgt = dfma(g1, wb, wgt); wgt = dfma(g2, wc, wgt);
    wgt = dfma(g3, wd, wgt); wgt = dfma(g4, we, wgt);

    u64 wi = dmul(wgt, inv);
    vx = dfma(dx, wi, vx);
    vy = dfma(dy, wi, vy);
    vz = dfma(dz, wi, vz);
}

// Warp-autonomous pipeline: each warp owns a 4-stage cp.async ring of
// 4-point tiles (400B padded point stride). Lane = (point p=l>>3, pair j=l&7);
// each lane runs pairs j and j+8, then an 8-lane shfl_xor reduce.
#define RING_D      4
#define PT_STRIDE   400u
#define STAGE_B     1600u
#define WARP_SMEM   6400u

__global__ void __launch_bounds__(256, 3)
velvec_kernel(const float* __restrict__ pos, const float* __restrict__ nbr,
              const float* __restrict__ W1, const float* __restrict__ b1,
              const float* __restrict__ W2, const float* __restrict__ b2,
              const float* __restrict__ W3, const float* __restrict__ b3,
              float* __restrict__ out, int N, int ntiles)
{
    extern __shared__ char ring[];             // 8 * 6400 = 51200 B
    __shared__ __align__(16) u64 sw[56];

    int tid = threadIdx.x;

    // weights: load + pack + pre-scale once per block
    if (tid < 56) {
        float v;
        if (tid < 20) {
            int j = tid >> 2, i = tid & 3;
            v = (i < 3) ? __ldg(W1 + 3 * j + i) : __ldg(b1 + j);
        } else if (tid < 50) {
            int t = tid - 20, j = t / 6, i = t - 6 * j;
            v = (i < 5) ? 0.5f * __ldg(W2 + 5 * j + i) : __ldg(b2 + j);
        } else if (tid < 55) {
            v = 0.5f * __ldg(W3 + tid - 50);
        } else {
            v = __ldg(b3);
        }
        unsigned int u = __float_as_uint(v);
        sw[tid] = ((u64)u << 32) | (u64)u;
    }
    __syncthreads();

    int wid = tid >> 5;
    int l = tid & 31;
    int p = l >> 3;            // point within tile
    int j = l & 7;             // pair index (does j and j+8)
    uint32_t swb = smem_u32(sw);
    uint32_t wbase = smem_u32(ring) + (uint32_t)wid * WARP_SMEM;

    // cp.async chunk mapping: chunk m = l + 32c of the 1536B tile slab
    uint32_t doff[3];
    int goff[3];
#pragma unroll
    for (int c = 0; c < 3; c++) {
        int m = l + 32 * c;
        int pp = m / 24, r = m % 24;
        doff[c] = (uint32_t)pp * PT_STRIDE + (uint32_t)r * 16u;
        goff[c] = m * 16;
    }
    uint32_t rd = (uint32_t)p * PT_STRIDE + (uint32_t)j * 24u;

    int gw = blockIdx.x * 8 + wid;
    int GW = gridDim.x * 8;
    const char* gn = (const char*)nbr;
    long long nbytes = (long long)N * 384;

    // prologue: prefetch RING_D-1 tiles into stages 0..2
    int tp = gw;
#pragma unroll
    for (int k = 0; k < RING_D - 1; k++) {
        if (tp < ntiles) {
            long long base = (long long)tp * 1536;
#pragma unroll
            for (int c = 0; c < 3; c++)
                cp16(wbase + (uint32_t)k * STAGE_B + doff[c], gn + base + goff[c],
                     base + goff[c] + 16 <= nbytes);
        }
        cp_commit();
        tp += GW;
    }

    int k = 0;
    for (int t = gw; t < ntiles; t += GW, k++) {
        cp_wait2();
        __syncwarp();

        int n = 4 * t + p;
        float px = 0.f, py = 0.f, pz = 0.f;
        if (n < N) {
            px = __ldg(pos + 3 * n + 0);
            py = __ldg(pos + 3 * n + 1);
            pz = __ldg(pos + 3 * n + 2);
        }
        u64 npx = pk2(-px, -px), npy = pk2(-py, -py), npz = pk2(-pz, -pz);
        u64 vx = 0ULL, vy = 0ULL, vz = 0ULL;

        uint32_t sb = wbase + (uint32_t)(k & 3) * STAGE_B + rd;
        {   // pair j  (neighbors 2j, 2j+1): 6 floats at sb
            float x0, y0, z0, x1, y1, z1;
            lds_f2(sb + 0, x0, y0);
            lds_f2(sb + 8, z0, x1);
            lds_f2(sb + 16, y1, z1);
            pair_step(pk2(x0, x1), pk2(y0, y1), pk2(z0, z1),
                      npx, npy, npz, swb, vx, vy, vz);
        }
        {   // pair j+8 at sb + 192
            float x0, y0, z0, x1, y1, z1;
            lds_f2(sb + 192, x0, y0);
            lds_f2(sb + 200, z0, x1);
            lds_f2(sb + 208, y1, z1);
            pair_step(pk2(x0, x1), pk2(y0, y1), pk2(z0, z1),
                      npx, npy, npz, swb, vx, vy, vz);
        }

        float x0, x1, y0, y1, z0, z1;
        upk(vx, x0, x1); upk(vy, y0, y1); upk(vz, z0, z1);
        float fx = x0 + x1, fy = y0 + y1, fz = z0 + z1;
#pragma unroll
        for (int d = 1; d < 8; d <<= 1) {
            fx += __shfl_xor_sync(0xFFFFFFFFu, fx, d);
            fy += __shfl_xor_sync(0xFFFFFFFFu, fy, d);
            fz += __shfl_xor_sync(0xFFFFFFFFu, fz, d);
        }

        if (j == 0 && n < N) {
            float d2 = fmaf(fx, fx, fmaf(fy, fy, fz * fz));
            d2 = fmaxf(d2, 1e-24f);
            float r = rsqrtf(d2);
            r = r * fmaf(-0.5f * d2 * r, r, 1.5f);  // one Newton step
            out[3 * n + 0] = fx * r;
            out[3 * n + 1] = fy * r;
            out[3 * n + 2] = fz * r;
        }

        __syncwarp();   // everyone done reading the stage reused below
        if (tp < ntiles) {
            long long base = (long long)tp * 1536;
            uint32_t st = (uint32_t)((k + 3) & 3) * STAGE_B;
#pragma unroll
            for (int c = 0; c < 3; c++)
                cp16(wbase + st + doff[c], gn + base + goff[c],
                     base + goff[c] + 16 <= nbytes);
        }
        cp_commit();
        tp += GW;
    }
}

extern "C" void kernel_launch(void* const* d_in, const int* in_sizes, int n_in,
                              void* d_out, int out_size)
{
    const float* pos = (const float*)d_in[0];
    const float* nbr = (const float*)d_in[1];
    const float* W1  = (const float*)d_in[2];
    const float* b1  = (const float*)d_in[3];
    const float* W2  = (const float*)d_in[4];
    const float* b2  = (const float*)d_in[5];
    const float* W3  = (const float*)d_in[6];
    const float* b3  = (const float*)d_in[7];
    float* out = (float*)d_out;

    static bool attr_set = false;
    if (!attr_set) {
        cudaFuncSetAttribute(velvec_kernel,
                             cudaFuncAttributeMaxDynamicSharedMemorySize, 51200);
        attr_set = true;
    }

    int N = in_sizes[0] / 3;            // positions is [N,3]
    int ntiles = (N + 3) / 4;           // 4 points per warp-tile
    int grid = 444;                      // 3 persistent blocks per SM
    velvec_kernel<<<grid, 256, 51200>>>(pos, nbr, W1, b1, W2, b2, W3, b3,
                                        out, N, ntiles);
}